// round 10
// baseline (speedup 1.0000x reference)
#include <cuda_runtime.h>
#include <cuda_bf16.h>

#define DOF     300000
#define E4      75000          // DOF/4 float4 elements
#define NB      8
#define TPB     512
#define NWARP   (TPB/32)
#define NCHUNK  4              // float4 per thread
#define NEWTON  6
#define NRED    6
#define BPBMAX  64

// ---- persistent device scratch (self-resetting across graph replays) ----
// Invariant at each launch boundary: all slots except the last-used (5) have
// g_scnt==0 and g_acc==0; slot 5 is reset during slot 0 of the next run.
__device__ float g_acc[NEWTON][NB][8];   // zero-initialized at load
__device__ int   g_scnt[NEWTON][NB];     // zero-initialized at load

__device__ __forceinline__ float warp_red(float v)
{
#pragma unroll
    for (int o = 16; o; o >>= 1) v += __shfl_down_sync(0xffffffffu, v, o);
    return v;
}

__device__ __forceinline__ float frcp(float x)
{
    float r;
    asm("rcp.approx.ftz.f32 %0, %1;" : "=f"(r) : "f"(x));
    return r;
}

// ---- proven R8 barrier: atomic accumulate, per-slot counter, self-reset ----
__device__ __forceinline__ void bar6(float* acc, int batch, int blk, int bpb, int slot,
                                     float (*s_w)[NRED], float* s_bc, int tid)
{
    int lane = tid & 31, wid = tid >> 5;
#pragma unroll
    for (int k = 0; k < NRED; k++) acc[k] = warp_red(acc[k]);
    if (lane == 0) {
#pragma unroll
        for (int k = 0; k < NRED; k++) s_w[wid][k] = acc[k];
    }
    __syncthreads();
    if (tid == 0) {
#pragma unroll
        for (int k = 0; k < NRED; k++) {
            float s = 0.f;
#pragma unroll
            for (int j = 0; j < NWARP; j++) s += s_w[j][k];
            atomicAdd(&g_acc[slot][batch][k], s);
        }
        __threadfence();
        atomicAdd(&g_scnt[slot][batch], 1);
        while (*((volatile int*)&g_scnt[slot][batch]) < bpb) __nanosleep(64);
        __threadfence();
#pragma unroll
        for (int k = 0; k < NRED; k++) s_bc[k] = __ldcg(&g_acc[slot][batch][k]);

        // Reset the PREVIOUS slot (blk 0 only) — safe per R8 reasoning.
        if (blk == 0) {
            int prev = (slot + NEWTON - 1) % NEWTON;
#pragma unroll
            for (int k = 0; k < NRED; k++) g_acc[prev][batch][k] = 0.f;
            __threadfence();
            atomicExch(&g_scnt[prev][batch], 0);
        }
    }
    __syncthreads();
}

// ---- single persistent kernel ----
__global__ void __launch_bounds__(TPB, 2)
k_solver(const float* __restrict__ F, const float* __restrict__ U0,
         const float* __restrict__ Kd, const int* __restrict__ fixed,
         int nfixed, float* __restrict__ OUT, int bpb)
{
    extern __shared__ float4 sh4[];
    float4* s_kf = sh4;                    // Kd with fixed dofs zeroed
    float4* s_f  = sh4 + NCHUNK * TPB;     // raw f
    float4* s_du = sh4 + 2 * NCHUNK * TPB; // Newton step du
    __shared__ float s_w[NWARP][NRED];
    __shared__ float s_bc[NRED];

    const int tid   = threadIdx.x;
    const int batch = blockIdx.x / bpb;
    const int blk   = blockIdx.x - batch * bpb;
    const int base  = blk * TPB + tid;
    const int grp   = bpb * TPB;

    const float4* __restrict__ kd4 = (const float4*)Kd;
    const float4* __restrict__ f4  = ((const float4*)F) + batch * E4;
    const float4* __restrict__ u04 = ((const float4*)U0) + batch * E4;

    const float al[6] = {1.f, 0.5f, 0.25f, 0.125f, 0.0625f, 0.05f};
    const float4 z4 = make_float4(0.f, 0.f, 0.f, 0.f);

    float4 u[NCHUNK];

    // ---- one-time load: u0 -> regs, Kd + f -> smem ----
#pragma unroll
    for (int c = 0; c < NCHUNK; c++) {
        int e = c * grp + base;
        float4 U = z4, KF = z4, FV = z4;
        if (e < E4) {
            KF = __ldg(kd4 + e);
            FV = __ldg(f4 + e);
            U  = __ldg(u04 + e);
        }
        s_kf[c * TPB + tid] = KF;
        s_f [c * TPB + tid] = FV;
        u[c] = U;
    }
    __syncthreads();

    // ---- patch fixed dofs: zero owned s_kf scalars (kfc==0 <=> fixed/OOB) ----
    for (int i = tid; i < nfixed; i += TPB) {
        int dd = __ldg(fixed + i);
        if (dd >= 0 && dd < DOF) {
            int e = dd >> 2, comp = dd & 3;
            int c = e / grp;
            int o = e - c * grp;
            if ((o / TPB) == blk)
                ((float*)&s_kf[c * TPB + (o % TPB)])[comp] = 0.f;
        }
    }
    __syncthreads();

    for (int nit = 0; nit < NEWTON; ++nit) {
        // moments: M0=SumA^2 M1=SumA*w M2=SumA*v M3=Sumw^2 M4=Sumw*v M5=Sumv^2
        // with w = u*d^2, v = d^3
        float acc[NRED];
#pragma unroll
        for (int k = 0; k < NRED; k++) acc[k] = 0.f;

#pragma unroll
        for (int c = 0; c < NCHUNK; c++) {
            float4 kf = s_kf[c * TPB + tid];
            float4 fv = s_f [c * TPB + tid];
            float4 D4;
#pragma unroll
            for (int comp = 0; comp < 4; comp++) {
                float kfc = (&kf.x)[comp];
                float fvc = (&fv.x)[comp];
                float uu  = (&u[c].x)[comp];
                bool  fr  = (kfc > 0.f);
                float u2  = uu * uu;
                float t04 = 0.4f * u2;                        // 4*beta*u^2
                float g   = fmaf(-kfc, uu, fvc);
                g         = fmaf(-t04, uu, g);                // f - k u - 4b u^3
                float A   = fr ? g : 0.f;                     // filtered residual
                float h   = fmaf(1.2f, u2, kfc);              // k + 12b u^2
                float hs  = fr ? h : 1.f;
                float d   = -A * frcp(hs);                    // exact CG limit
                float d2  = d * d;
                float w   = uu * d2;
                float v   = d2 * d;
                (&D4.x)[comp] = d;
                acc[0] = fmaf(A, A, acc[0]);
                acc[1] = fmaf(A, w, acc[1]);
                acc[2] = fmaf(A, v, acc[2]);
                acc[3] = fmaf(w, w, acc[3]);
                acc[4] = fmaf(w, v, acc[4]);
                acc[5] = fmaf(v, v, acc[5]);
            }
            s_du[c * TPB + tid] = D4;
        }

        bar6(acc, batch, blk, bpb, nit, s_w, s_bc, tid);

        // P-terms with constants folded scalar-side
        float P0 = s_bc[0];
        float P1 = -1.2f  * s_bc[1];   // Sum A*C,  C = -1.2 w
        float P2 = -0.4f  * s_bc[2];   // Sum A*D,  D = -0.4 v
        float P3 =  1.44f * s_bc[3];   // Sum C^2
        float P4 =  0.48f * s_bc[4];   // Sum C*D
        float P5 =  0.16f * s_bc[5];   // Sum D^2

        // ||res(a)||^2 = S0 + S1 a + ... + S6 a^6   (B == A identity)
        float S0 = P0;
        float S1 = 2.f * P0;
        float S2 = fmaf(2.f, P1, P0);
        float S3 = 2.f * (P1 + P2);
        float S4 = fmaf(2.f, P2, P3);
        float S5 = 2.f * P4;
        float S6 = P5;

        // first improving alpha (smallest trial index); default ALPHA_MIN
        float ab = 0.05f;
#pragma unroll
        for (int t = 5; t >= 0; t--) {
            float a = al[t];
            float vv = S6;
            vv = fmaf(vv, a, S5);
            vv = fmaf(vv, a, S4);
            vv = fmaf(vv, a, S3);
            vv = fmaf(vv, a, S2);
            vv = fmaf(vv, a, S1);
            vv = fmaf(vv, a, S0);
            if (vv < S0) ab = a;
        }

        // u += alpha * du
#pragma unroll
        for (int c = 0; c < NCHUNK; c++) {
            float4 D = s_du[c * TPB + tid];
            u[c].x = fmaf(ab, D.x, u[c].x);
            u[c].y = fmaf(ab, D.y, u[c].y);
            u[c].z = fmaf(ab, D.z, u[c].z);
            u[c].w = fmaf(ab, D.w, u[c].w);
        }
    }

    // write final u
#pragma unroll
    for (int c = 0; c < NCHUNK; c++) {
        int e = c * grp + base;
        if (e < E4) ((float4*)OUT)[batch * E4 + e] = u[c];
    }
}

extern "C" void kernel_launch(void* const* d_in, const int* in_sizes, int n_in,
                              void* d_out, int out_size)
{
    const float* F     = (const float*)d_in[0];
    const float* U0    = (const float*)d_in[1];
    const float* Kd    = (const float*)d_in[2];
    const int*   fixed = (const int*)d_in[3];
    int nfixed = in_sizes[3];
    float* out = (float*)d_out;

    int dev = 0;
    cudaGetDevice(&dev);
    int sm = 148;
    cudaDeviceGetAttribute(&sm, cudaDevAttrMultiProcessorCount, dev);

    int bpb = (2 * sm) / NB;                                  // 2 CTAs/SM, co-resident
    int need = (E4 + TPB * NCHUNK - 1) / (TPB * NCHUNK);      // 37
    if (bpb < need) bpb = need;
    if (bpb > BPBMAX) bpb = BPBMAX;

    size_t shmem = (size_t)3 * NCHUNK * TPB * sizeof(float4); // 96 KB
    cudaFuncSetAttribute(k_solver, cudaFuncAttributeMaxDynamicSharedMemorySize, (int)shmem);

    k_solver<<<bpb * NB, TPB, shmem>>>(F, U0, Kd, fixed, nfixed, out, bpb);
}

// round 13
// speedup vs baseline: 1.0848x; 1.0848x over previous
#include <cuda_runtime.h>
#include <cuda_bf16.h>

#define DOF     300000
#define E4      75000          // DOF/4 float4 elements
#define NB      8
#define TPB     512
#define NWARP   (TPB/32)
#define NCHUNK  4              // float4 per thread
#define NEWTON  6
#define NRED    6
#define BPBMAX  64

typedef unsigned long long u64t;

// ---- persistent device scratch (self-resetting across graph replays) ----
// Invariant at each launch boundary: all slots except the last-used (5) have
// g_scnt==0 and g_acc==0; slot 5 is reset during slot 0 of the next run.
__device__ float g_acc[NEWTON][NB][8];   // zero-initialized at load
__device__ int   g_scnt[NEWTON][NB];     // zero-initialized at load

// ---- packed f32x2 helpers (FFMA2 path: PTX-only) ----
__device__ __forceinline__ u64t fma2(u64t a, u64t b, u64t c)
{ u64t r; asm("fma.rn.f32x2 %0,%1,%2,%3;" : "=l"(r) : "l"(a), "l"(b), "l"(c)); return r; }
__device__ __forceinline__ u64t mul2(u64t a, u64t b)
{ u64t r; asm("mul.rn.f32x2 %0,%1,%2;" : "=l"(r) : "l"(a), "l"(b)); return r; }
__device__ __forceinline__ u64t pk2(float lo, float hi)
{ u64t r; asm("mov.b64 %0,{%1,%2};" : "=l"(r) : "f"(lo), "f"(hi)); return r; }
__device__ __forceinline__ void upk2(u64t v, float& lo, float& hi)
{ asm("mov.b64 {%0,%1},%2;" : "=f"(lo), "=f"(hi) : "l"(v)); }

__device__ __forceinline__ float warp_red(float v)
{
#pragma unroll
    for (int o = 16; o; o >>= 1) v += __shfl_down_sync(0xffffffffu, v, o);
    return v;
}

__device__ __forceinline__ float frcp(float x)
{
    float r;
    asm("rcp.approx.ftz.f32 %0, %1;" : "=f"(r) : "f"(x));
    return r;
}

// ---- proven R8/R10 barrier: atomic accumulate, per-slot counter, self-reset ----
__device__ __forceinline__ void bar6(float* acc, int batch, int blk, int bpb, int slot,
                                     float (*s_w)[NRED], float* s_bc, int tid)
{
    int lane = tid & 31, wid = tid >> 5;
#pragma unroll
    for (int k = 0; k < NRED; k++) acc[k] = warp_red(acc[k]);
    if (lane == 0) {
#pragma unroll
        for (int k = 0; k < NRED; k++) s_w[wid][k] = acc[k];
    }
    __syncthreads();
    if (tid == 0) {
#pragma unroll
        for (int k = 0; k < NRED; k++) {
            float s = 0.f;
#pragma unroll
            for (int j = 0; j < NWARP; j++) s += s_w[j][k];
            atomicAdd(&g_acc[slot][batch][k], s);
        }
        __threadfence();
        atomicAdd(&g_scnt[slot][batch], 1);
        while (*((volatile int*)&g_scnt[slot][batch]) < bpb) __nanosleep(64);
        __threadfence();
#pragma unroll
        for (int k = 0; k < NRED; k++) s_bc[k] = __ldcg(&g_acc[slot][batch][k]);

        // Reset the PREVIOUS slot (blk 0 only) — safe per R8 reasoning.
        if (blk == 0) {
            int prev = (slot + NEWTON - 1) % NEWTON;
#pragma unroll
            for (int k = 0; k < NRED; k++) g_acc[prev][batch][k] = 0.f;
            __threadfence();
            atomicExch(&g_scnt[prev][batch], 0);
        }
    }
    __syncthreads();
}

// ---- single persistent kernel ----
__global__ void __launch_bounds__(TPB, 2)
k_solver(const float* __restrict__ F, const float* __restrict__ U0,
         const float* __restrict__ Kd, const int* __restrict__ fixed,
         int nfixed, float* __restrict__ OUT, int bpb)
{
    extern __shared__ float4 sh4[];
    float4* s_kf = sh4;                    // NEGATED Kd; fixed/OOB patched to +1
    float4* s_f  = sh4 + NCHUNK * TPB;     // f; fixed/OOB patched to 0
    float4* s_du = sh4 + 2 * NCHUNK * TPB; // Newton step du
    __shared__ float s_w[NWARP][NRED];
    __shared__ float s_bc[NRED];

    const int tid   = threadIdx.x;
    const int batch = blockIdx.x / bpb;
    const int blk   = blockIdx.x - batch * bpb;
    const int base  = blk * TPB + tid;
    const int grp   = bpb * TPB;

    const float4* __restrict__ kd4 = (const float4*)Kd;
    const float4* __restrict__ f4  = ((const float4*)F) + batch * E4;
    const float4* __restrict__ u04 = ((const float4*)U0) + batch * E4;

    const float al[6] = {1.f, 0.5f, 0.25f, 0.125f, 0.0625f, 0.05f};

    ulonglong2 u[NCHUNK];   // packed (lo,hi) pairs == natural float order

    // ---- one-time load: u0 -> regs, -Kd + f -> smem ----
#pragma unroll
    for (int c = 0; c < NCHUNK; c++) {
        int e = c * grp + base;
        float4 KF, FV, U;
        if (e < E4) {
            float4 kd = __ldg(kd4 + e);
            KF = make_float4(-kd.x, -kd.y, -kd.z, -kd.w);
            FV = __ldg(f4 + e);
            U  = __ldg(u04 + e);
        } else {
            KF = make_float4(1.f, 1.f, 1.f, 1.f);
            FV = make_float4(0.f, 0.f, 0.f, 0.f);
            U  = make_float4(0.f, 0.f, 0.f, 0.f);
        }
        s_kf[c * TPB + tid] = KF;
        s_f [c * TPB + tid] = FV;
        u[c] = *reinterpret_cast<ulonglong2*>(&U);
    }
    __syncthreads();

    // ---- patch fixed dofs: kfn=+1, f=0 (kfn>0 <=> fixed/OOB) ----
    for (int i = tid; i < nfixed; i += TPB) {
        int dd = __ldg(fixed + i);
        if (dd >= 0 && dd < DOF) {
            int e = dd >> 2, comp = dd & 3;
            int c = e / grp;
            int o = e - c * grp;
            if ((o / TPB) == blk) {
                int s = c * TPB + (o % TPB);
                ((float*)&s_kf[s])[comp] = 1.f;
                ((float*)&s_f [s])[comp] = 0.f;
            }
        }
    }
    __syncthreads();

    // ---- zero u (working copy) wherever kfn>0; output re-patched at end ----
#pragma unroll
    for (int c = 0; c < NCHUNK; c++) {
        float4 KF = s_kf[c * TPB + tid];
        float a0, a1, a2, a3;
        upk2(u[c].x, a0, a1);
        upk2(u[c].y, a2, a3);
        if (KF.x > 0.f) a0 = 0.f;
        if (KF.y > 0.f) a1 = 0.f;
        if (KF.z > 0.f) a2 = 0.f;
        if (KF.w > 0.f) a3 = 0.f;
        u[c].x = pk2(a0, a1);
        u[c].y = pk2(a2, a3);
    }

    const u64t m04 = pk2(-0.4f, -0.4f);
    const u64t m12 = pk2(-1.2f, -1.2f);

    for (int nit = 0; nit < NEWTON; ++nit) {
        // packed moments: a0=SumA^2 a1=SumA*w a2=SumA*v a3=Sumw^2 a4=Sumw*v a5=Sumv^2
        // with w = u*d^2, v = d^3, d = -A/h  (free dofs); fixed/OOB contribute 0.
        u64t pa0 = 0, pa1 = 0, pa2 = 0, pa3 = 0, pa4 = 0, pa5 = 0;

#pragma unroll
        for (int c = 0; c < NCHUNK; c++) {
            ulonglong2 kk = *reinterpret_cast<ulonglong2*>(&s_kf[c * TPB + tid]);
            ulonglong2 ff = *reinterpret_cast<ulonglong2*>(&s_f [c * TPB + tid]);
            ulonglong2 dd;
#pragma unroll
            for (int hp = 0; hp < 2; hp++) {
                u64t up  = hp ? u[c].y : u[c].x;
                u64t kfn = hp ? kk.y   : kk.x;
                u64t fv  = hp ? ff.y   : ff.x;
                u64t us = mul2(up, up);            // u^2
                u64t g  = fma2(kfn, up, fv);       // f - k u   (kfn = -k)
                u64t u3 = mul2(us, up);
                g       = fma2(u3, m04, g);        // - 0.4 u^3  -> A
                u64t hn = fma2(us, m12, kfn);      // -(k + 1.2 u^2) = -h  (fixed: +1)
                float g0, g1, h0, h1;
                upk2(g,  g0, g1);
                upk2(hn, h0, h1);
                float d0 = g0 * frcp(h0);          // g/(-h) = -A/h
                float d1 = g1 * frcp(h1);
                u64t dp = pk2(d0, d1);
                u64t d2 = mul2(dp, dp);
                u64t w  = mul2(up, d2);
                u64t v  = mul2(d2, dp);
                pa0 = fma2(g, g, pa0);
                pa1 = fma2(g, w, pa1);
                pa2 = fma2(g, v, pa2);
                pa3 = fma2(w, w, pa3);
                pa4 = fma2(w, v, pa4);
                pa5 = fma2(v, v, pa5);
                if (hp) dd.y = dp; else dd.x = dp;
            }
            *reinterpret_cast<ulonglong2*>(&s_du[c * TPB + tid]) = dd;
        }

        // collapse packed halves -> 6 scalars
        float acc[NRED];
        {
            float lo, hi;
            upk2(pa0, lo, hi); acc[0] = lo + hi;
            upk2(pa1, lo, hi); acc[1] = lo + hi;
            upk2(pa2, lo, hi); acc[2] = lo + hi;
            upk2(pa3, lo, hi); acc[3] = lo + hi;
            upk2(pa4, lo, hi); acc[4] = lo + hi;
            upk2(pa5, lo, hi); acc[5] = lo + hi;
        }

        bar6(acc, batch, blk, bpb, nit, s_w, s_bc, tid);

        // P-terms with constants folded scalar-side
        float P0 = s_bc[0];
        float P1 = -1.2f  * s_bc[1];   // Sum A*C,  C = -1.2 w
        float P2 = -0.4f  * s_bc[2];   // Sum A*D,  D = -0.4 v
        float P3 =  1.44f * s_bc[3];   // Sum C^2
        float P4 =  0.48f * s_bc[4];   // Sum C*D
        float P5 =  0.16f * s_bc[5];   // Sum D^2

        // ||res(a)||^2 = S0 + S1 a + ... + S6 a^6   (B == A identity)
        float S0 = P0;
        float S1 = 2.f * P0;
        float S2 = fmaf(2.f, P1, P0);
        float S3 = 2.f * (P1 + P2);
        float S4 = fmaf(2.f, P2, P3);
        float S5 = 2.f * P4;
        float S6 = P5;

        // first improving alpha (smallest trial index); default ALPHA_MIN
        float ab = 0.05f;
#pragma unroll
        for (int t = 5; t >= 0; t--) {
            float a = al[t];
            float vv = S6;
            vv = fmaf(vv, a, S5);
            vv = fmaf(vv, a, S4);
            vv = fmaf(vv, a, S3);
            vv = fmaf(vv, a, S2);
            vv = fmaf(vv, a, S1);
            vv = fmaf(vv, a, S0);
            if (vv < S0) ab = a;
        }

        // u += alpha * du  (packed)
        u64t abp = pk2(ab, ab);
#pragma unroll
        for (int c = 0; c < NCHUNK; c++) {
            ulonglong2 dd = *reinterpret_cast<ulonglong2*>(&s_du[c * TPB + tid]);
            u[c].x = fma2(abp, dd.x, u[c].x);
            u[c].y = fma2(abp, dd.y, u[c].y);
        }
    }

    // ---- write final u ----
#pragma unroll
    for (int c = 0; c < NCHUNK; c++) {
        int e = c * grp + base;
        if (e < E4)
            *reinterpret_cast<ulonglong2*>(&((float4*)OUT)[batch * E4 + e]) = u[c];
    }
    __syncthreads();

    // ---- restore u0 at fixed dofs (block owns these elements; sync above
    //      orders the vector store before this scalar overwrite) ----
    for (int i = tid; i < nfixed; i += TPB) {
        int dd = __ldg(fixed + i);
        if (dd >= 0 && dd < DOF) {
            int e = dd >> 2;
            int c = e / grp;
            int o = e - c * grp;
            if ((o / TPB) == blk)
                OUT[batch * DOF + dd] = __ldg(&U0[batch * DOF + dd]);
        }
    }
}

extern "C" void kernel_launch(void* const* d_in, const int* in_sizes, int n_in,
                              void* d_out, int out_size)
{
    const float* F     = (const float*)d_in[0];
    const float* U0    = (const float*)d_in[1];
    const float* Kd    = (const float*)d_in[2];
    const int*   fixed = (const int*)d_in[3];
    int nfixed = in_sizes[3];
    float* out = (float*)d_out;

    int dev = 0;
    cudaGetDevice(&dev);
    int sm = 148;
    cudaDeviceGetAttribute(&sm, cudaDevAttrMultiProcessorCount, dev);

    int bpb = (2 * sm) / NB;                                  // 2 CTAs/SM, co-resident
    int need = (E4 + TPB * NCHUNK - 1) / (TPB * NCHUNK);      // 37
    if (bpb < need) bpb = need;
    if (bpb > BPBMAX) bpb = BPBMAX;

    size_t shmem = (size_t)3 * NCHUNK * TPB * sizeof(float4); // 96 KB
    cudaFuncSetAttribute(k_solver, cudaFuncAttributeMaxDynamicSharedMemorySize, (int)shmem);

    k_solver<<<bpb * NB, TPB, shmem>>>(F, U0, Kd, fixed, nfixed, out, bpb);
}